// round 1
// baseline (speedup 1.0000x reference)
#include <cuda_runtime.h>
#include <cuda_bf16.h>

// Problem constants (fixed by setup_inputs)
#define BSZ   4
#define CCH   256
#define HH    32
#define WW    32
#define HWSZ  1024      // HH*WW
#define NQ    300
#define NCLS  80
#define TOPK  150
#define SORTN 512       // next pow2 >= NQ
// batched_h = batched_w = 512, grid step = 512/32 = 16

// Scratch (no allocations allowed)
__device__ int d_src[BSZ][HWSZ];
__device__ int d_objnum[BSZ];

// ---------------------------------------------------------------------------
// Kernel 1: per-batch control — cls max, top-k, boxes, point mask, compaction
// Launch: <<<BSZ, 1024>>>
// ---------------------------------------------------------------------------
__global__ void __launch_bounds__(1024, 1)
prep_kernel(const float* __restrict__ coord,       // (BSZ,NQ,4)
            const float* __restrict__ cls_logits,  // (BSZ,NQ,NCLS)
            const int*   __restrict__ sizes,       // (BSZ,2) int32
            const unsigned char* __restrict__ padmask) // (BSZ,HWSZ) all-zero bools
{
    __shared__ unsigned long long sk[SORTN];
    __shared__ float4 boxes[TOPK];
    __shared__ int sc[HWSZ];
    __shared__ unsigned char mk[HWSZ];

    const int b   = blockIdx.x;
    const int tid = threadIdx.x;

    // --- 1) per-query class max, build sort keys -------------------------
    if (tid < SORTN) {
        unsigned long long key;
        if (tid < NQ) {
            const float* row = cls_logits + (size_t)(b * NQ + tid) * NCLS;
            float m = row[0];
            #pragma unroll 4
            for (int k = 1; k < NCLS; k++) m = fmaxf(m, row[k]);
            // monotone float->uint map (handles negatives too)
            unsigned int vb = __float_as_uint(m);
            vb = (vb & 0x80000000u) ? ~vb : (vb | 0x80000000u);
            // composite: larger value first; tie -> smaller index first
            key = ((unsigned long long)vb << 32)
                | (unsigned long long)(0xFFFFFFFFu - (unsigned)tid);
            key = ~key;   // ascending sort of ~key == descending by (value,index)
        } else {
            key = 0xFFFFFFFFFFFFFFFFull;   // pads sort last
        }
        sk[tid] = key;
    }
    __syncthreads();

    // --- 2) bitonic ascending sort of sk[0..511] -------------------------
    for (int k = 2; k <= SORTN; k <<= 1) {
        for (int j = k >> 1; j > 0; j >>= 1) {
            if (tid < SORTN) {
                int ixj = tid ^ j;
                if (ixj > tid) {
                    bool up = ((tid & k) == 0);
                    unsigned long long a = sk[tid], c2 = sk[ixj];
                    if ((up && a > c2) || (!up && a < c2)) {
                        sk[tid] = c2; sk[ixj] = a;
                    }
                }
            }
            __syncthreads();
        }
    }

    // --- 3) top-150 boxes, scaled to true sizes --------------------------
    const float ts0 = (float)sizes[b * 2 + 0];
    const float ts1 = (float)sizes[b * 2 + 1];
    if (tid < TOPK) {
        unsigned long long key = ~sk[tid];
        int q = (int)(0xFFFFFFFFu - (unsigned)(key & 0xFFFFFFFFull));
        const float* bx = coord + (size_t)(b * NQ + q) * 4;
        float cx = bx[0], cy = bx[1], bw = bx[2], bh = bx[3];
        // 0.5f*bw is exact -> one rounding per op, bit-matches XLA
        float x1 = ts0 * (cx - 0.5f * bw);
        float y1 = ts1 * (cy - 0.5f * bh);
        float x2 = ts0 * (cx + 0.5f * bw);
        float y2 = ts1 * (cy + 0.5f * bh);
        boxes[tid] = make_float4(x1, y1, x2, y2);
    }
    __syncthreads();

    // --- 4) sampled-grid point-in-box mask (one point per thread) --------
    {
        const int p = tid;                 // 0..1023
        const int i = p >> 5;              // row in 32x32
        const int j = p & 31;              // col
        const float gy = (float)(i * 16);  // ih = i*512//32
        const float gx = (float)(j * 16);
        bool inbox = false;
        for (int kk = 0; kk < TOPK; kk++) {
            float4 bb = boxes[kk];
            if (gx > bb.x && gx < bb.z && gy > bb.y && gy < bb.w) { inbox = true; break; }
        }
        int om = (!inbox) | (padmask[b * HWSZ + p] != 0);
        mk[p] = (unsigned char)om;
        sc[p] = om;
    }
    __syncthreads();

    // --- 5) inclusive scan over 1024 entries (Hillis-Steele) -------------
    for (int off = 1; off < HWSZ; off <<= 1) {
        int v = sc[tid];
        if (tid >= off) v += sc[tid - off];
        __syncthreads();
        sc[tid] = v;
        __syncthreads();
    }

    // --- 6) compaction: masked positions in ascending order --------------
    if (mk[tid]) d_src[b][sc[tid] - 1] = tid;
    if (tid == HWSZ - 1) d_objnum[b] = sc[tid];
}

// ---------------------------------------------------------------------------
// Kernel 2: gather + zero-pad. Block = one (p,b) pair; threads over channels.
// Launch: <<<HWSZ*BSZ, CCH>>>
// out layout: [sparse_key (1024,4,256) fp32][sparse_key_pos (1024,4,256) fp32]
// ---------------------------------------------------------------------------
__global__ void __launch_bounds__(CCH, 8)
gather_kernel(const float* __restrict__ x,
              const float* __restrict__ pos,
              float* __restrict__ out)
{
    const int pb = blockIdx.x;     // p*BSZ + b
    const int b  = pb & (BSZ - 1);
    const int p  = pb >> 2;
    const int c  = threadIdx.x;

    float vk = 0.0f, vp = 0.0f;
    if (p < d_objnum[b]) {
        const int s = d_src[b][p];
        const size_t base = (size_t)b * CCH * HWSZ + (size_t)c * HWSZ + s;
        vk = __ldg(x + base);
        vp = __ldg(pos + base);
    }
    const int o = pb * CCH + c;
    out[o] = vk;
    out[HWSZ * BSZ * CCH + o] = vp;
}

// ---------------------------------------------------------------------------
extern "C" void kernel_launch(void* const* d_in, const int* in_sizes, int n_in,
                              void* d_out, int out_size)
{
    const float* x        = (const float*)d_in[0];  // (4,256,32,32)
    const float* pos      = (const float*)d_in[1];  // (4,256,32,32)
    const unsigned char* msk = (const unsigned char*)d_in[2]; // (4,32,32) bool zeros
    const float* coord    = (const float*)d_in[3];  // (4,300,4)
    const float* clsl     = (const float*)d_in[4];  // (4,300,80)
    const int*   sizes    = (const int*)d_in[5];    // (4,2) int32
    float* out = (float*)d_out;

    prep_kernel<<<BSZ, 1024>>>(coord, clsl, sizes, msk);
    gather_kernel<<<HWSZ * BSZ, CCH>>>(x, pos, out);
}

// round 2
// speedup vs baseline: 1.5355x; 1.5355x over previous
#include <cuda_runtime.h>
#include <cuda_bf16.h>

// Problem constants (fixed by setup_inputs)
#define BSZ   4
#define CCH   256
#define HH    32
#define WW    32
#define HWSZ  1024      // HH*WW
#define NQ    300
#define NCLS  80
#define TOPK  150
// batched_h = batched_w = 512, grid step = 512/32 = 16

// Scratch (no allocations allowed)
__device__ int d_src[BSZ][HWSZ];
__device__ int d_objnum[BSZ];

// ---------------------------------------------------------------------------
// Kernel 1: per-batch control — cls max, top-k SET via pairwise rank,
//           boxes, sampled point mask, ballot-scan compaction.
// Launch: <<<BSZ, 1024>>>   (~6 barriers total, no sort)
// ---------------------------------------------------------------------------
__global__ void __launch_bounds__(1024, 1)
prep_kernel(const float* __restrict__ coord,       // (BSZ,NQ,4)
            const float* __restrict__ cls_logits,  // (BSZ,NQ,NCLS)
            const int*   __restrict__ sizes,       // (BSZ,2) int32
            const unsigned char* __restrict__ padmask) // (BSZ,HWSZ)
{
    __shared__ float  svals[NQ];
    __shared__ float4 boxes[TOPK];
    __shared__ int    nsel;
    __shared__ int    wsum[32];

    const int b    = blockIdx.x;
    const int tid  = threadIdx.x;
    const int lane = tid & 31;
    const int wid  = tid >> 5;

    if (tid == 0) nsel = 0;

    // --- 1) per-query class max (max is exact: order-independent) --------
    if (tid < NQ) {
        const float4* row = (const float4*)(cls_logits + (size_t)(b * NQ + tid) * NCLS);
        float4 v = row[0];
        float m = fmaxf(fmaxf(v.x, v.y), fmaxf(v.z, v.w));
        #pragma unroll
        for (int k = 1; k < NCLS / 4; k++) {
            v = row[k];
            m = fmaxf(m, fmaxf(fmaxf(v.x, v.y), fmaxf(v.z, v.w)));
        }
        svals[tid] = m;
    }
    __syncthreads();

    // --- 2) top-150 SET via pairwise rank (exact top_k tie semantics) ----
    const float ts0 = (float)sizes[b * 2 + 0];
    const float ts1 = (float)sizes[b * 2 + 1];
    if (tid < NQ) {
        const float vi = svals[tid];
        int rank = 0;
        #pragma unroll 4
        for (int j = 0; j < NQ; j++) {
            float vj = svals[j];
            rank += (vj > vi) || (vj == vi && j < tid);
        }
        if (rank < TOPK) {
            const float* bx = coord + (size_t)(b * NQ + tid) * 4;
            float cx = bx[0], cy = bx[1], bw = bx[2], bh = bx[3];
            // 0.5f*bw exact -> one rounding per op, matches XLA
            float x1 = ts0 * (cx - 0.5f * bw);
            float y1 = ts1 * (cy - 0.5f * bh);
            float x2 = ts0 * (cx + 0.5f * bw);
            float y2 = ts1 * (cy + 0.5f * bh);
            int pos = atomicAdd(&nsel, 1);   // order irrelevant: mask is any()
            boxes[pos] = make_float4(x1, y1, x2, y2);
        }
    }
    __syncthreads();

    // --- 3) sampled-grid point-in-box mask (one point per thread) --------
    const int i = tid >> 5;            // row in 32x32
    const int j = tid & 31;            // col
    const float gy = (float)(i * 16);  // ih = i*512//32
    const float gx = (float)(j * 16);
    bool inbox = false;
    const int nb = nsel;               // == TOPK
    for (int kk = 0; kk < nb; kk++) {
        float4 bb = boxes[kk];
        if (gx > bb.x && gx < bb.z && gy > bb.y && gy < bb.w) { inbox = true; break; }
    }
    const int om = (!inbox) | (padmask[b * HWSZ + tid] != 0);

    // --- 4) ballot-based scan + compaction (ascending index order) -------
    unsigned bal = __ballot_sync(0xffffffffu, om);
    if (lane == 0) wsum[wid] = __popc(bal);
    __syncthreads();
    if (wid == 0) {
        int v = wsum[lane];
        #pragma unroll
        for (int o = 1; o < 32; o <<= 1) {
            int t = __shfl_up_sync(0xffffffffu, v, o);
            if (lane >= o) v += t;
        }
        wsum[lane] = v;   // inclusive
    }
    __syncthreads();
    const int warp_off = wid ? wsum[wid - 1] : 0;
    const int pre = __popc(bal & ((1u << lane) - 1u));
    if (om) d_src[b][warp_off + pre] = tid;
    if (tid == 1023) d_objnum[b] = wsum[31];
}

// ---------------------------------------------------------------------------
// Kernel 2: tiled gather+transpose.
// Block = (b, 32-p tile, 64-c tile). Read: lanes along gathered s (dense,
// ascending -> sector sharing). Write: lanes along c (fully coalesced).
// Grid: 4*32*4 = 512 blocks, 256 threads (32x8).
// out layout: [sparse_key (1024,4,256)][sparse_key_pos (1024,4,256)] fp32
// ---------------------------------------------------------------------------
#define PT 32   // p per tile
#define CT 64   // c per tile
#define TS 65   // smem row stride (odd -> conflict-free columns)

__global__ void __launch_bounds__(256, 4)
gather_kernel(const float* __restrict__ x,
              const float* __restrict__ pos,
              float* __restrict__ out)
{
    __shared__ float tk[PT * TS];
    __shared__ float tp[PT * TS];
    __shared__ int   ss[PT];

    const int blk = blockIdx.x;
    const int b   = blk & (BSZ - 1);
    const int pt  = (blk >> 2) & 31;     // p-tile index (0..31)
    const int ct  = blk >> 7;            // c-tile index (0..3)
    const int p0  = pt * PT;
    const int c0  = ct * CT;

    const int tx = threadIdx.x & 31;     // p-lane
    const int ty = threadIdx.x >> 5;     // warp id (0..7)

    // stage gathered source indices (-1 => zero fill)
    if (threadIdx.x < PT) {
        const int p = p0 + threadIdx.x;
        ss[threadIdx.x] = (p < d_objnum[b]) ? d_src[b][p] : -1;
    }
    __syncthreads();

    const int s = ss[tx];

    // read phase: 8 warps x 8 iters cover 64 channels; lanes along s
    #pragma unroll
    for (int it = 0; it < 8; it++) {
        const int cl = it * 8 + ty;      // 0..63
        const int c  = c0 + cl;
        const size_t base = ((size_t)(b * CCH + c) << 10);
        float vk = 0.0f, vp = 0.0f;
        if (s >= 0) {
            vk = __ldg(x + base + s);
            vp = __ldg(pos + base + s);
        }
        tk[tx * TS + cl] = vk;
        tp[tx * TS + cl] = vp;
    }
    __syncthreads();

    // write phase: lanes along c (coalesced). tid -> (pl, cl)
    const int cl  = threadIdx.x & 63;
    const int pl0 = threadIdx.x >> 6;    // 0..3
    const size_t out2 = (size_t)HWSZ * BSZ * CCH;
    #pragma unroll
    for (int pass = 0; pass < 8; pass++) {
        const int pl = pass * 4 + pl0;   // 0..31
        const size_t o = (size_t)(p0 + pl) * (BSZ * CCH) + b * CCH + c0 + cl;
        out[o]        = tk[pl * TS + cl];
        out[out2 + o] = tp[pl * TS + cl];
    }
}

// ---------------------------------------------------------------------------
extern "C" void kernel_launch(void* const* d_in, const int* in_sizes, int n_in,
                              void* d_out, int out_size)
{
    const float* x        = (const float*)d_in[0];  // (4,256,32,32)
    const float* pos      = (const float*)d_in[1];  // (4,256,32,32)
    const unsigned char* msk = (const unsigned char*)d_in[2]; // (4,32,32) bool
    const float* coord    = (const float*)d_in[3];  // (4,300,4)
    const float* clsl     = (const float*)d_in[4];  // (4,300,80)
    const int*   sizes    = (const int*)d_in[5];    // (4,2) int32
    float* out = (float*)d_out;

    prep_kernel<<<BSZ, 1024>>>(coord, clsl, sizes, msk);
    gather_kernel<<<BSZ * 32 * 4, 256>>>(x, pos, out);
}

// round 3
// speedup vs baseline: 2.0909x; 1.3617x over previous
#include <cuda_runtime.h>
#include <cuda_bf16.h>

// Problem constants (fixed by setup_inputs)
#define BSZ   4
#define CCH   256
#define HWSZ  1024      // 32*32
#define NQ    300
#define NCLS  80
#define TOPK  150
// batched_h = batched_w = 512, grid step = 16

__device__ int d_src[BSZ][HWSZ];
__device__ int d_objnum[BSZ];

// ---------------------------------------------------------------------------
// Kernel 1: control. cls max -> top-150 set (pairwise rank) -> box raster into
// 32-word bitmask (atomicOr) -> ballot-scan compaction.  <<<4, 1024>>>
// ---------------------------------------------------------------------------
__global__ void __launch_bounds__(1024, 1)
prep_kernel(const float* __restrict__ coord,       // (BSZ,NQ,4)
            const float* __restrict__ cls_logits,  // (BSZ,NQ,NCLS)
            const int*   __restrict__ sizes,       // (BSZ,2)
            const unsigned char* __restrict__ padmask) // (BSZ,HWSZ)
{
    __shared__ float    svals[NQ];
    __shared__ unsigned rowmask[32];
    __shared__ int      wsum[32];

    const int b    = blockIdx.x;
    const int tid  = threadIdx.x;
    const int lane = tid & 31;
    const int wid  = tid >> 5;

    if (tid < 32) rowmask[tid] = 0u;

    // --- 1) per-query class max (order-independent, exact) ---------------
    if (tid < NQ) {
        const float4* row = (const float4*)(cls_logits + (size_t)(b * NQ + tid) * NCLS);
        float4 v = row[0];
        float m = fmaxf(fmaxf(v.x, v.y), fmaxf(v.z, v.w));
        #pragma unroll
        for (int k = 1; k < NCLS / 4; k++) {
            v = row[k];
            m = fmaxf(m, fmaxf(fmaxf(v.x, v.y), fmaxf(v.z, v.w)));
        }
        svals[tid] = m;
    }
    __syncthreads();

    // --- 2) top-150 set via pairwise rank; rasterize selected boxes ------
    const float ts0 = (float)sizes[b * 2 + 0];
    const float ts1 = (float)sizes[b * 2 + 1];
    if (tid < NQ) {
        const float vi = svals[tid];
        int rank = 0;
        #pragma unroll 4
        for (int j = 0; j < NQ; j++) {
            float vj = svals[j];
            rank += (vj > vi) || (vj == vi && j < tid);
        }
        if (rank < TOPK) {
            const float* bx = coord + (size_t)(b * NQ + tid) * 4;
            float cx = bx[0], cy = bx[1], bw = bx[2], bh = bx[3];
            // one rounding per op (matches XLA); *0.0625f is exact
            float x1 = ts0 * (cx - 0.5f * bw);
            float y1 = ts1 * (cy - 0.5f * bh);
            float x2 = ts0 * (cx + 0.5f * bw);
            float y2 = ts1 * (cy + 0.5f * bh);
            // j*16 > x1  <=>  j > x1/16  (exact);  j*16 < x2 <=> j < x2/16
            int jlo = (int)floorf(x1 * 0.0625f) + 1;
            int jhi = (int)ceilf (x2 * 0.0625f) - 1;
            int ilo = (int)floorf(y1 * 0.0625f) + 1;
            int ihi = (int)ceilf (y2 * 0.0625f) - 1;
            jlo = max(jlo, 0);  jhi = min(jhi, 31);
            ilo = max(ilo, 0);  ihi = min(ihi, 31);
            if (jlo <= jhi && ilo <= ihi) {
                unsigned jmask = ((jhi == 31) ? 0xFFFFFFFFu : ((1u << (jhi + 1)) - 1u))
                               & ~((1u << jlo) - 1u);
                for (int i = ilo; i <= ihi; i++) atomicOr(&rowmask[i], jmask);
            }
        }
    }
    __syncthreads();

    // --- 3) per-point mask + ballot compaction ---------------------------
    const int i = tid >> 5, j = tid & 31;
    const int inbox = (rowmask[i] >> j) & 1u;
    const int om = (!inbox) | (padmask[b * HWSZ + tid] != 0);

    unsigned bal = __ballot_sync(0xffffffffu, om);
    if (lane == 0) wsum[wid] = __popc(bal);
    __syncthreads();
    if (wid == 0) {
        int v = wsum[lane];
        #pragma unroll
        for (int o = 1; o < 32; o <<= 1) {
            int t = __shfl_up_sync(0xffffffffu, v, o);
            if (lane >= o) v += t;
        }
        wsum[lane] = v;   // inclusive
    }
    __syncthreads();
    const int warp_off = wid ? wsum[wid - 1] : 0;
    const int pre = __popc(bal & ((1u << lane) - 1u));
    if (om) d_src[b][warp_off + pre] = tid;
    if (tid == 1023) d_objnum[b] = wsum[31];
}

// ---------------------------------------------------------------------------
// Kernel 2: gather. Tile = (b, 32 p, 32 c). FAST PATH: tile fully beyond
// objnum -> stream float4 zeros (the common case). SLOW PATH: smem transpose,
// reads with lanes along gathered s, 128-bit coalesced stores.
// Grid: 4*32*8 = 1024 blocks, 256 threads.
// out: [sparse_key (1024,4,256)][sparse_key_pos (1024,4,256)] fp32
// ---------------------------------------------------------------------------
#define PT 32
#define CT 32
#define TS 33   // smem row stride (floats): conflict-free both phases

__global__ void __launch_bounds__(256, 8)
gather_kernel(const float* __restrict__ x,
              const float* __restrict__ pos,
              float* __restrict__ out)
{
    const int blk = blockIdx.x;
    const int b   = blk & (BSZ - 1);
    const int pt  = (blk >> 2) & 31;     // 0..31
    const int ct  = blk >> 7;            // 0..7
    const int p0  = pt * PT;
    const int c0  = ct * CT;
    const int tid = threadIdx.x;

    const int objnum = d_objnum[b];
    const size_t out2 = (size_t)HWSZ * BSZ * CCH;

    if (p0 >= objnum) {
        // ---- fast path: pure zero-fill, float4 stores -------------------
        const int cl4 = tid & 7;         // 8 x float4 = 32 channels
        const int pl  = tid >> 3;        // 0..31
        const size_t o = (size_t)(p0 + pl) * (BSZ * CCH) + b * CCH + c0 + cl4 * 4;
        const float4 z = make_float4(0.f, 0.f, 0.f, 0.f);
        *(float4*)(out + o)        = z;
        *(float4*)(out + out2 + o) = z;
        return;
    }

    // ---- slow path: gather + transpose ----------------------------------
    __shared__ float tk[PT * TS];
    __shared__ float tp[PT * TS];
    __shared__ int   ss[PT];

    if (tid < PT) {
        const int p = p0 + tid;
        ss[tid] = (p < objnum) ? d_src[b][p] : -1;
    }
    __syncthreads();

    const int tx = tid & 31;             // p-lane (along s)
    const int ty = tid >> 5;             // warp 0..7
    const int s  = ss[tx];

    #pragma unroll
    for (int it = 0; it < 4; it++) {
        const int cl = it * 8 + ty;      // 0..31
        const size_t base = ((size_t)(b * CCH + c0 + cl) << 10);
        float vk = 0.f, vp = 0.f;
        if (s >= 0) {
            vk = __ldg(x + base + s);
            vp = __ldg(pos + base + s);
        }
        tk[tx * TS + cl] = vk;
        tp[tx * TS + cl] = vp;
    }
    __syncthreads();

    // write: thread = (pl, cl4); 4 scalar LDS (conflict-free) -> STG.128
    const int cl4 = tid & 7;
    const int pl  = tid >> 3;
    float4 vk4, vp4;
    vk4.x = tk[pl * TS + cl4 * 4 + 0];
    vk4.y = tk[pl * TS + cl4 * 4 + 1];
    vk4.z = tk[pl * TS + cl4 * 4 + 2];
    vk4.w = tk[pl * TS + cl4 * 4 + 3];
    vp4.x = tp[pl * TS + cl4 * 4 + 0];
    vp4.y = tp[pl * TS + cl4 * 4 + 1];
    vp4.z = tp[pl * TS + cl4 * 4 + 2];
    vp4.w = tp[pl * TS + cl4 * 4 + 3];
    const size_t o = (size_t)(p0 + pl) * (BSZ * CCH) + b * CCH + c0 + cl4 * 4;
    *(float4*)(out + o)        = vk4;
    *(float4*)(out + out2 + o) = vp4;
}

// ---------------------------------------------------------------------------
extern "C" void kernel_launch(void* const* d_in, const int* in_sizes, int n_in,
                              void* d_out, int out_size)
{
    const float* x        = (const float*)d_in[0];  // (4,256,32,32)
    const float* pos      = (const float*)d_in[1];  // (4,256,32,32)
    const unsigned char* msk = (const unsigned char*)d_in[2]; // (4,32,32)
    const float* coord    = (const float*)d_in[3];  // (4,300,4)
    const float* clsl     = (const float*)d_in[4];  // (4,300,80)
    const int*   sizes    = (const int*)d_in[5];    // (4,2)
    float* out = (float*)d_out;

    prep_kernel<<<BSZ, 1024>>>(coord, clsl, sizes, msk);
    gather_kernel<<<BSZ * 32 * 8, 256>>>(x, pos, out);
}